// round 3
// baseline (speedup 1.0000x reference)
#include <cuda_runtime.h>

// Problem constants
#define L_   4096
#define C_   512
#define H_   8
#define D_   64
#define NB   4
#define NHT  32            // NB * H_
#define KS_  9
#define SPLITS 16
#define INV_PI 0.31830988618379067154f

// Scratch (static device globals — allocation-free per harness rules)
__device__ float g_q[(size_t)NB * H_ * L_ * D_];      // 32 MB
__device__ float g_k[(size_t)NB * H_ * L_ * D_];      // 32 MB
__device__ float g_v[(size_t)NB * H_ * L_ * D_];      // 32 MB
__device__ float g_part[(size_t)SPLITS * NHT * D_ * D_];  // 8 MB
__device__ float g_attn[(size_t)NHT * D_ * D_];       // 512 KB
__device__ float g_mid[(size_t)NB * L_ * C_];         // 32 MB

// ---------------------------------------------------------------------------
// SGEMM: C[M,N] = A[M,K] @ B[K,N] + bias[N]
// MODE 0: epilogue scatters into g_q/g_k/g_v as [N,H,L,D]   (QKV projection)
// MODE 1: A is g_mid, epilogue writes Cout row-major        (output projection)
// BM=BN=128, BK=16, 8x8 register tile, 256 threads.
// Assumes M%128==0, N%128==0, K%16==0 (true for both calls).
// ---------------------------------------------------------------------------
template <int MODE>
__global__ __launch_bounds__(256) void sgemm_kernel(
    const float* __restrict__ A, const float* __restrict__ B,
    const float* __restrict__ bias, float* __restrict__ Cout,
    int M, int N, int K)
{
    const int BM = 128, BN = 128, BK = 16;
    __shared__ float As[BK][BM];
    __shared__ float Bs[BK][BN];

    const float* Aptr = (MODE == 1) ? (const float*)g_mid : A;

    int tid = threadIdx.x;
    int bc = blockIdx.x;     // N tile
    int br = blockIdx.y;     // M tile
    int tr = tid / 16;       // 0..15 (row group)
    int tc = tid % 16;       // 0..15 (col group)

    // A tile load mapping: 128x16 floats -> 512 float4, 2 per thread
    int arow = tid / 4;            // 0..63
    int acol = (tid % 4) * 4;      // 0,4,8,12
    // B tile load mapping: 16x128 floats -> 512 float4, 2 per thread
    int brow = tid / 32;           // 0..7
    int bcol = (tid % 32) * 4;     // 0..124

    float acc[8][8];
#pragma unroll
    for (int i = 0; i < 8; i++)
#pragma unroll
        for (int j = 0; j < 8; j++) acc[i][j] = 0.f;

    const float* Ablk = Aptr + (size_t)br * BM * K;
    const float* Bblk = B + (size_t)bc * BN;

    for (int kk = 0; kk < K; kk += BK) {
#pragma unroll
        for (int p = 0; p < 2; p++) {
            int r = arow + p * 64;
            float4 t = *(const float4*)(Ablk + (size_t)r * K + kk + acol);
            As[acol + 0][r] = t.x;
            As[acol + 1][r] = t.y;
            As[acol + 2][r] = t.z;
            As[acol + 3][r] = t.w;
        }
#pragma unroll
        for (int p = 0; p < 2; p++) {
            int r = brow + p * 8;
            *(float4*)&Bs[r][bcol] =
                *(const float4*)(Bblk + (size_t)(kk + r) * N + bcol);
        }
        __syncthreads();

#pragma unroll
        for (int kb = 0; kb < BK; kb++) {
            float ra[8], rb[8];
            *(float4*)&ra[0] = *(const float4*)&As[kb][tr * 8];
            *(float4*)&ra[4] = *(const float4*)&As[kb][tr * 8 + 4];
            *(float4*)&rb[0] = *(const float4*)&Bs[kb][tc * 8];
            *(float4*)&rb[4] = *(const float4*)&Bs[kb][tc * 8 + 4];
#pragma unroll
            for (int i = 0; i < 8; i++)
#pragma unroll
                for (int j = 0; j < 8; j++)
                    acc[i][j] = fmaf(ra[i], rb[j], acc[i][j]);
        }
        __syncthreads();
    }

    // Epilogue
#pragma unroll
    for (int i = 0; i < 8; i++) {
        int row = br * BM + tr * 8 + i;
#pragma unroll
        for (int j = 0; j < 8; j++) {
            int col = bc * BN + tc * 8 + j;
            float v = acc[i][j] + bias[col];
            if (MODE == 0) {
                // col = s*512 + h*64 + d ; row = n*L + l
                int s = col >> 9;
                int h = (col >> 6) & 7;
                int d = col & 63;
                int n = row >> 12;
                int l = row & (L_ - 1);
                float* dst = (s == 0) ? g_q : ((s == 1) ? g_k : g_v);
                dst[(((size_t)n * H_ + h) * L_ + l) * D_ + d] = v;
            } else {
                Cout[(size_t)row * N + col] = v;
            }
        }
    }
}

// ---------------------------------------------------------------------------
// attn partial: for each (n,h), attn[d,e] = sum_l knorm[l,d] * v[l,e]
// grid (SPLITS, NHT), 256 threads; k rows l2-normalized in smem.
// partial[split][nh][64*64]
// ---------------------------------------------------------------------------
__global__ __launch_bounds__(256) void kv_attn_partial_kernel()
{
    __shared__ float ks[32][68];
    __shared__ float vs[32][68];
    __shared__ float invn[32];

    int tid = threadIdx.x;
    int split = blockIdx.x;
    int nh = blockIdx.y;
    int ty = tid / 16, tx = tid % 16;
    int d0 = ty * 4, e0 = tx * 4;

    float acc[4][4];
#pragma unroll
    for (int i = 0; i < 4; i++)
#pragma unroll
        for (int j = 0; j < 4; j++) acc[i][j] = 0.f;

    const float* kp = g_k + (size_t)nh * L_ * D_;
    const float* vp = g_v + (size_t)nh * L_ * D_;
    int lbase = split * (L_ / SPLITS);

    for (int t = 0; t < (L_ / SPLITS) / 32; t++) {   // 8 tiles of 32 rows
        int l0 = lbase + t * 32;
#pragma unroll
        for (int p = 0; p < 2; p++) {
            int fi = tid + p * 256;          // 0..511
            int r = fi >> 4;
            int c = (fi & 15) * 4;
            *(float4*)&ks[r][c] = *(const float4*)(kp + (size_t)(l0 + r) * D_ + c);
            *(float4*)&vs[r][c] = *(const float4*)(vp + (size_t)(l0 + r) * D_ + c);
        }
        __syncthreads();

        if (tid < 32) {
            float s = 0.f;
#pragma unroll
            for (int d = 0; d < 64; d++) {
                float x = ks[tid][d];
                s = fmaf(x, x, s);
            }
            invn[tid] = 1.0f / sqrtf(s);
        }
        __syncthreads();

#pragma unroll 4
        for (int l = 0; l < 32; l++) {
            float inv = invn[l];
            float kd[4];
#pragma unroll
            for (int i = 0; i < 4; i++) kd[i] = ks[l][d0 + i] * inv;
            float4 ve = *(const float4*)&vs[l][e0];
            float vej[4] = {ve.x, ve.y, ve.z, ve.w};
#pragma unroll
            for (int i = 0; i < 4; i++)
#pragma unroll
                for (int j = 0; j < 4; j++)
                    acc[i][j] = fmaf(kd[i], vej[j], acc[i][j]);
        }
        __syncthreads();
    }

    float* out = g_part + ((size_t)split * NHT + nh) * (D_ * D_);
#pragma unroll
    for (int i = 0; i < 4; i++)
#pragma unroll
        for (int j = 0; j < 4; j++)
            out[(d0 + i) * 64 + (e0 + j)] = acc[i][j];
}

// Deterministic reduction of split partials; folds INV_PI into attn.
__global__ __launch_bounds__(256) void attn_reduce_kernel()
{
    int idx = blockIdx.x * 256 + threadIdx.x;     // < NHT*4096
    int nh = idx >> 12;
    int rem = idx & 4095;
    float s = 0.f;
#pragma unroll
    for (int sp = 0; sp < SPLITS; sp++)
        s += g_part[((size_t)sp * NHT + nh) * 4096 + rem];
    g_attn[idx] = INV_PI * s;
}

// ---------------------------------------------------------------------------
// out kernel: per (n,h), per 32-row L chunk:
//   pre = 0.5*v + (1/||q||) * (q @ attn)     (attn already has INV_PI folded)
//   out = pre/||pre|| + depthwise_conv9(v)
// writes g_mid in [N, L, C] layout (C = h*64+e).
// 128 threads: 32 rows x 4 col-groups of 16.
// ---------------------------------------------------------------------------
__global__ __launch_bounds__(128) void out_kernel(const float* __restrict__ wdc)
{
    __shared__ float attn_s[64][64];   // 16 KB
    __shared__ float qs[32][68];       // padded
    __shared__ float vs[40][68];       // 32 rows + 8 halo
    __shared__ float invq[32];
    __shared__ float wc[KS_];

    int tid = threadIdx.x;
    int nh = blockIdx.y;
    int n = nh >> 3, h = nh & 7;
    int l0 = blockIdx.x * 32;

    const float* qp = g_q + (size_t)nh * L_ * D_;
    const float* vp = g_v + (size_t)nh * L_ * D_;
    const float* ap = g_attn + (size_t)nh * 4096;

    // attn: 1024 float4, 8/thread
#pragma unroll
    for (int p = 0; p < 8; p++) {
        int fi = tid + p * 128;
        int r = fi >> 4, c = (fi & 15) * 4;
        *(float4*)&attn_s[r][c] = *(const float4*)(ap + r * 64 + c);
    }
    // q: 512 float4, 4/thread
#pragma unroll
    for (int p = 0; p < 4; p++) {
        int fi = tid + p * 128;
        int r = fi >> 4, c = (fi & 15) * 4;
        *(float4*)&qs[r][c] = *(const float4*)(qp + (size_t)(l0 + r) * D_ + c);
    }
    // v with halo: 640 float4
    for (int fi = tid; fi < 40 * 16; fi += 128) {
        int r = fi >> 4, c = (fi & 15) * 4;
        int gl = l0 - 4 + r;
        float4 val = make_float4(0.f, 0.f, 0.f, 0.f);
        if (gl >= 0 && gl < L_)
            val = *(const float4*)(vp + (size_t)gl * D_ + c);
        *(float4*)&vs[r][c] = val;
    }
    if (tid < KS_) wc[tid] = wdc[h * KS_ + tid];
    __syncthreads();

    if (tid < 32) {
        float s = 0.f;
#pragma unroll
        for (int d = 0; d < 64; d++) {
            float x = qs[tid][d];
            s = fmaf(x, x, s);
        }
        invq[tid] = 1.0f / sqrtf(s);
    }
    __syncthreads();

    int r = tid >> 2;        // row 0..31
    int p4 = tid & 3;        // col group
    int e0 = p4 * 16;

    float acc[16];
#pragma unroll
    for (int j = 0; j < 16; j++) acc[j] = 0.f;

#pragma unroll 8
    for (int d = 0; d < 64; d++) {
        float qv = qs[r][d];
        float4 a0 = *(const float4*)&attn_s[d][e0];
        float4 a1 = *(const float4*)&attn_s[d][e0 + 4];
        float4 a2 = *(const float4*)&attn_s[d][e0 + 8];
        float4 a3 = *(const float4*)&attn_s[d][e0 + 12];
        acc[0]  = fmaf(qv, a0.x, acc[0]);
        acc[1]  = fmaf(qv, a0.y, acc[1]);
        acc[2]  = fmaf(qv, a0.z, acc[2]);
        acc[3]  = fmaf(qv, a0.w, acc[3]);
        acc[4]  = fmaf(qv, a1.x, acc[4]);
        acc[5]  = fmaf(qv, a1.y, acc[5]);
        acc[6]  = fmaf(qv, a1.z, acc[6]);
        acc[7]  = fmaf(qv, a1.w, acc[7]);
        acc[8]  = fmaf(qv, a2.x, acc[8]);
        acc[9]  = fmaf(qv, a2.y, acc[9]);
        acc[10] = fmaf(qv, a2.z, acc[10]);
        acc[11] = fmaf(qv, a2.w, acc[11]);
        acc[12] = fmaf(qv, a3.x, acc[12]);
        acc[13] = fmaf(qv, a3.y, acc[13]);
        acc[14] = fmaf(qv, a3.z, acc[14]);
        acc[15] = fmaf(qv, a3.w, acc[15]);
    }

    float iq = invq[r];
    float pre[16];
    float ssq = 0.f;
#pragma unroll
    for (int jc = 0; jc < 4; jc++) {
        float4 vv = *(const float4*)&vs[r + 4][e0 + jc * 4];
        float p0 = fmaf(0.5f, vv.x, acc[jc * 4 + 0] * iq);
        float p1 = fmaf(0.5f, vv.y, acc[jc * 4 + 1] * iq);
        float p2 = fmaf(0.5f, vv.z, acc[jc * 4 + 2] * iq);
        float p3 = fmaf(0.5f, vv.w, acc[jc * 4 + 3] * iq);
        pre[jc * 4 + 0] = p0; pre[jc * 4 + 1] = p1;
        pre[jc * 4 + 2] = p2; pre[jc * 4 + 3] = p3;
        ssq = fmaf(p0, p0, ssq);
        ssq = fmaf(p1, p1, ssq);
        ssq = fmaf(p2, p2, ssq);
        ssq = fmaf(p3, p3, ssq);
    }
    // full-row sum across the 4 threads owning this row (lanes 4k..4k+3)
    ssq += __shfl_xor_sync(0xffffffffu, ssq, 1);
    ssq += __shfl_xor_sync(0xffffffffu, ssq, 2);
    float inv2 = 1.0f / sqrtf(ssq);

    float dc[16];
#pragma unroll
    for (int j = 0; j < 16; j++) dc[j] = 0.f;
#pragma unroll
    for (int t = 0; t < KS_; t++) {
        float w = wc[t];
#pragma unroll
        for (int jc = 0; jc < 4; jc++) {
            float4 vv = *(const float4*)&vs[r + t][e0 + jc * 4];
            dc[jc * 4 + 0] = fmaf(w, vv.x, dc[jc * 4 + 0]);
            dc[jc * 4 + 1] = fmaf(w, vv.y, dc[jc * 4 + 1]);
            dc[jc * 4 + 2] = fmaf(w, vv.z, dc[jc * 4 + 2]);
            dc[jc * 4 + 3] = fmaf(w, vv.w, dc[jc * 4 + 3]);
        }
    }

    float* mp = g_mid + ((size_t)(n * L_ + l0 + r)) * C_ + h * D_ + e0;
#pragma unroll
    for (int jc = 0; jc < 4; jc++) {
        float4 o;
        o.x = fmaf(pre[jc * 4 + 0], inv2, dc[jc * 4 + 0]);
        o.y = fmaf(pre[jc * 4 + 1], inv2, dc[jc * 4 + 1]);
        o.z = fmaf(pre[jc * 4 + 2], inv2, dc[jc * 4 + 2]);
        o.w = fmaf(pre[jc * 4 + 3], inv2, dc[jc * 4 + 3]);
        *(float4*)(mp + jc * 4) = o;
    }
}

// ---------------------------------------------------------------------------
extern "C" void kernel_launch(void* const* d_in, const int* in_sizes, int n_in,
                              void* d_out, int out_size)
{
    const float* x       = (const float*)d_in[0];   // [4,4096,512]
    const float* w_qkv   = (const float*)d_in[1];   // [512,1536]
    const float* b_qkv   = (const float*)d_in[2];   // [1536]
    const float* w_dconv = (const float*)d_in[3];   // [8,1,9,1]
    const float* w_proj  = (const float*)d_in[4];   // [512,512]
    const float* b_proj  = (const float*)d_in[5];   // [512]
    float* out = (float*)d_out;                      // [4,4096,512]

    const int M = NB * L_;       // 16384

    // 1. QKV projection (+bias), scatter to q/k/v [N,H,L,D]
    sgemm_kernel<0><<<dim3((3 * C_) / 128, M / 128), 256>>>(
        x, w_qkv, b_qkv, nullptr, M, 3 * C_, C_);

    // 2. attn partials: k l2norm fused; split-L for occupancy
    kv_attn_partial_kernel<<<dim3(SPLITS, NHT), 256>>>();

    // 3. deterministic reduce (+ INV_PI fold)
    attn_reduce_kernel<<<(NHT * D_ * D_) / 256, 256>>>();

    // 4. fused: q@attn (q-norm folded), 0.5v, row l2norm, depthwise conv, layout->[N,L,C]
    out_kernel<<<dim3(L_ / 32, NHT), 128>>>(w_dconv);

    // 5. output projection (+bias) -> d_out
    sgemm_kernel<1><<<dim3(C_ / 128, M / 128), 256>>>(
        nullptr, w_proj, b_proj, out, M, C_, C_);
}

// round 4
// speedup vs baseline: 2.1239x; 2.1239x over previous
#include <cuda_runtime.h>

// Problem constants
#define L_   4096
#define C_   512
#define H_   8
#define D_   64
#define NB   4
#define NHT  32            // NB * H_
#define KS_  9
#define SPLITS 16
#define INV_PI 0.31830988618379067154f

// Scratch (static device globals — allocation-free per harness rules)
__device__ float g_q[(size_t)NB * H_ * L_ * D_];
__device__ float g_k[(size_t)NB * H_ * L_ * D_];
__device__ float g_v[(size_t)NB * H_ * L_ * D_];
__device__ float g_part[(size_t)SPLITS * NHT * D_ * D_];
__device__ float g_attn[(size_t)NHT * D_ * D_];
__device__ float g_mid[(size_t)NB * L_ * C_];

// ---------------------------------------------------------------------------
// TF32 helpers
// ---------------------------------------------------------------------------
__device__ __forceinline__ float f2tf(float x) {
    unsigned y;
    asm("cvt.rna.tf32.f32 %0, %1;" : "=r"(y) : "f"(x));
    return __uint_as_float(y);
}

__device__ __forceinline__ void mma_tf32(float* c, const unsigned* a, const unsigned* b) {
    asm volatile(
        "mma.sync.aligned.m16n8k8.row.col.f32.tf32.tf32.f32 "
        "{%0,%1,%2,%3}, {%4,%5,%6,%7}, {%8,%9}, {%0,%1,%2,%3};\n"
        : "+f"(c[0]), "+f"(c[1]), "+f"(c[2]), "+f"(c[3])
        : "r"(a[0]), "r"(a[1]), "r"(a[2]), "r"(a[3]),
          "r"(b[0]), "r"(b[1]));
}

// ---------------------------------------------------------------------------
// TF32 tensor-core GEMM: C[M,N] = A[M,K] @ B[K,N] + bias[N]
// MODE 0: epilogue scatters into g_q/g_k/g_v as [N,H,L,D]   (QKV projection)
// MODE 1: A is g_mid, epilogue writes Cout row-major        (output projection)
// BM=BN=128, BK=16, 256 threads = 8 warps as 2(m) x 4(n), warp tile 64x32.
// Fragments: m16n8k8; As/Bs stored k-major with 132-float row pad
// (conflict-free fragment loads). Double-buffered smem w/ register prefetch.
// Requires M%128==0, N%128==0, K%16==0 (true for both calls).
// ---------------------------------------------------------------------------
template <int MODE>
__global__ __launch_bounds__(256) void tf32_gemm_kernel(
    const float* __restrict__ A, const float* __restrict__ B,
    const float* __restrict__ bias, float* __restrict__ Cout,
    int M, int N, int K)
{
    __shared__ alignas(16) float As[2][16][132];
    __shared__ alignas(16) float Bs[2][16][132];

    const float* Aptr = (MODE == 1) ? (const float*)g_mid : A;

    const int tid = threadIdx.x;
    const int lane = tid & 31;
    const int warp = tid >> 5;
    const int warp_m = warp >> 2;       // 0..1
    const int warp_n = warp & 3;        // 0..3
    const int g = lane >> 2;            // 0..7
    const int tig = lane & 3;           // 0..3

    const int bn = blockIdx.x;
    const int bm = blockIdx.y;

    // gmem load mapping
    const int arow = tid >> 2;          // 0..63
    const int acol = (tid & 3) * 4;     // 0,4,8,12
    const int brow = tid >> 5;          // 0..7
    const int bcol = (tid & 31) * 4;    // 0..124

    const float* Ablk = Aptr + (size_t)bm * 128 * K;
    const float* Bblk = B + (size_t)bn * 128;

    float acc[4][4][4];
#pragma unroll
    for (int mt = 0; mt < 4; mt++)
#pragma unroll
        for (int nt = 0; nt < 4; nt++)
#pragma unroll
            for (int i = 0; i < 4; i++) acc[mt][nt][i] = 0.f;

    // --- prologue: stage 0 direct gmem -> smem (with tf32 rounding) ---
    {
#pragma unroll
        for (int p = 0; p < 2; p++) {
            int r = arow + 64 * p;
            float4 t = *(const float4*)(Ablk + (size_t)r * K + acol);
            As[0][acol + 0][r] = f2tf(t.x);
            As[0][acol + 1][r] = f2tf(t.y);
            As[0][acol + 2][r] = f2tf(t.z);
            As[0][acol + 3][r] = f2tf(t.w);
        }
#pragma unroll
        for (int p = 0; p < 2; p++) {
            int r = brow + 8 * p;
            float4 t = *(const float4*)(Bblk + (size_t)r * N + bcol);
            float4 c = make_float4(f2tf(t.x), f2tf(t.y), f2tf(t.z), f2tf(t.w));
            *(float4*)&Bs[0][r][bcol] = c;
        }
    }
    __syncthreads();

    int buf = 0;
    for (int kk = 0; kk < K; kk += 16) {
        const bool has_next = (kk + 16) < K;
        float4 pa0, pa1, pb0, pb1;
        if (has_next) {
            pa0 = *(const float4*)(Ablk + (size_t)arow * K + (kk + 16) + acol);
            pa1 = *(const float4*)(Ablk + (size_t)(arow + 64) * K + (kk + 16) + acol);
            pb0 = *(const float4*)(Bblk + (size_t)(kk + 16 + brow) * N + bcol);
            pb1 = *(const float4*)(Bblk + (size_t)(kk + 16 + brow + 8) * N + bcol);
        }

        // --- compute: 2 k8 substeps from buffer `buf` ---
        const float (*Asb)[132] = As[buf];
        const float (*Bsb)[132] = Bs[buf];
#pragma unroll
        for (int ks = 0; ks < 2; ks++) {
            const int k0 = ks * 8;
            unsigned af[4][4], bf[4][2];
#pragma unroll
            for (int mt = 0; mt < 4; mt++) {
                int m0 = warp_m * 64 + mt * 16 + g;
                af[mt][0] = __float_as_uint(Asb[k0 + tig][m0]);
                af[mt][1] = __float_as_uint(Asb[k0 + tig][m0 + 8]);
                af[mt][2] = __float_as_uint(Asb[k0 + tig + 4][m0]);
                af[mt][3] = __float_as_uint(Asb[k0 + tig + 4][m0 + 8]);
            }
#pragma unroll
            for (int nt = 0; nt < 4; nt++) {
                int n0 = warp_n * 32 + nt * 8 + g;
                bf[nt][0] = __float_as_uint(Bsb[k0 + tig][n0]);
                bf[nt][1] = __float_as_uint(Bsb[k0 + tig + 4][n0]);
            }
#pragma unroll
            for (int mt = 0; mt < 4; mt++)
#pragma unroll
                for (int nt = 0; nt < 4; nt++)
                    mma_tf32(acc[mt][nt], af[mt], bf[nt]);
        }

        if (has_next) {
            int nb = buf ^ 1;
            As[nb][acol + 0][arow] = f2tf(pa0.x);
            As[nb][acol + 1][arow] = f2tf(pa0.y);
            As[nb][acol + 2][arow] = f2tf(pa0.z);
            As[nb][acol + 3][arow] = f2tf(pa0.w);
            As[nb][acol + 0][arow + 64] = f2tf(pa1.x);
            As[nb][acol + 1][arow + 64] = f2tf(pa1.y);
            As[nb][acol + 2][arow + 64] = f2tf(pa1.z);
            As[nb][acol + 3][arow + 64] = f2tf(pa1.w);
            float4 c0 = make_float4(f2tf(pb0.x), f2tf(pb0.y), f2tf(pb0.z), f2tf(pb0.w));
            float4 c1 = make_float4(f2tf(pb1.x), f2tf(pb1.y), f2tf(pb1.z), f2tf(pb1.w));
            *(float4*)&Bs[nb][brow][bcol] = c0;
            *(float4*)&Bs[nb][brow + 8][bcol] = c1;
            __syncthreads();
            buf = nb;
        }
    }

    // --- epilogue ---
#pragma unroll
    for (int mt = 0; mt < 4; mt++) {
        int r0 = bm * 128 + warp_m * 64 + mt * 16 + g;
#pragma unroll
        for (int nt = 0; nt < 4; nt++) {
            int col = bn * 128 + warp_n * 32 + nt * 8 + 2 * tig;   // even
            float b0 = bias[col];
            float b1 = bias[col + 1];
            float2 v01 = make_float2(acc[mt][nt][0] + b0, acc[mt][nt][1] + b1);
            float2 v23 = make_float2(acc[mt][nt][2] + b0, acc[mt][nt][3] + b1);
            if (MODE == 0) {
                int s = col >> 9;
                int h = (col >> 6) & 7;
                int d = col & 63;                 // even
                float* dst = (s == 0) ? g_q : ((s == 1) ? g_k : g_v);
                int n0r = r0 >> 12, l0r = r0 & (L_ - 1);
                size_t base = (((size_t)n0r * H_ + h) * L_) * D_ + d;
                *(float2*)(dst + base + (size_t)l0r * D_) = v01;
                *(float2*)(dst + base + (size_t)(l0r + 8) * D_) = v23;
            } else {
                *(float2*)(Cout + (size_t)r0 * N + col) = v01;
                *(float2*)(Cout + (size_t)(r0 + 8) * N + col) = v23;
            }
        }
    }
}

// ---------------------------------------------------------------------------
// attn partial: for each (n,h), attn[d,e] = sum_l knorm[l,d] * v[l,e]
// grid (SPLITS, NHT), 256 threads; k rows l2-normalized in smem.
// ---------------------------------------------------------------------------
__global__ __launch_bounds__(256) void kv_attn_partial_kernel()
{
    __shared__ float ks[32][68];
    __shared__ float vs[32][68];
    __shared__ float invn[32];

    int tid = threadIdx.x;
    int split = blockIdx.x;
    int nh = blockIdx.y;
    int ty = tid / 16, tx = tid % 16;
    int d0 = ty * 4, e0 = tx * 4;

    float acc[4][4];
#pragma unroll
    for (int i = 0; i < 4; i++)
#pragma unroll
        for (int j = 0; j < 4; j++) acc[i][j] = 0.f;

    const float* kp = g_k + (size_t)nh * L_ * D_;
    const float* vp = g_v + (size_t)nh * L_ * D_;
    int lbase = split * (L_ / SPLITS);

    for (int t = 0; t < (L_ / SPLITS) / 32; t++) {
        int l0 = lbase + t * 32;
#pragma unroll
        for (int p = 0; p < 2; p++) {
            int fi = tid + p * 256;
            int r = fi >> 4;
            int c = (fi & 15) * 4;
            *(float4*)&ks[r][c] = *(const float4*)(kp + (size_t)(l0 + r) * D_ + c);
            *(float4*)&vs[r][c] = *(const float4*)(vp + (size_t)(l0 + r) * D_ + c);
        }
        __syncthreads();

        if (tid < 32) {
            float s = 0.f;
#pragma unroll
            for (int d = 0; d < 64; d++) {
                float x = ks[tid][d];
                s = fmaf(x, x, s);
            }
            invn[tid] = 1.0f / sqrtf(s);
        }
        __syncthreads();

#pragma unroll 4
        for (int l = 0; l < 32; l++) {
            float inv = invn[l];
            float kd[4];
#pragma unroll
            for (int i = 0; i < 4; i++) kd[i] = ks[l][d0 + i] * inv;
            float4 ve = *(const float4*)&vs[l][e0];
            float vej[4] = {ve.x, ve.y, ve.z, ve.w};
#pragma unroll
            for (int i = 0; i < 4; i++)
#pragma unroll
                for (int j = 0; j < 4; j++)
                    acc[i][j] = fmaf(kd[i], vej[j], acc[i][j]);
        }
        __syncthreads();
    }

    float* out = g_part + ((size_t)split * NHT + nh) * (D_ * D_);
#pragma unroll
    for (int i = 0; i < 4; i++)
#pragma unroll
        for (int j = 0; j < 4; j++)
            out[(d0 + i) * 64 + (e0 + j)] = acc[i][j];
}

// Deterministic reduction of split partials; folds INV_PI into attn.
__global__ __launch_bounds__(256) void attn_reduce_kernel()
{
    int idx = blockIdx.x * 256 + threadIdx.x;
    int nh = idx >> 12;
    int rem = idx & 4095;
    float s = 0.f;
#pragma unroll
    for (int sp = 0; sp < SPLITS; sp++)
        s += g_part[((size_t)sp * NHT + nh) * 4096 + rem];
    g_attn[idx] = INV_PI * s;
}

// ---------------------------------------------------------------------------
// out kernel (restructured): 64 L-rows/block, 128 threads.
// Each thread owns 2 rows x 16 cols:
//   pre = 0.5*v + (1/||q||) * (q @ attn)     (attn has INV_PI folded)
//   out = pre/||pre|| + depthwise_conv9(v)
// v read directly from gmem via a 10-row register sliding window (L1-cached);
// attn+q staged in smem. Writes g_mid in [N,L,C] layout.
// ---------------------------------------------------------------------------
__global__ __launch_bounds__(128) void out_kernel(const float* __restrict__ wdc)
{
    __shared__ float attn_s[64][68];
    __shared__ float qs[64][68];
    __shared__ float invq[64];
    __shared__ float wc[16];

    const int tid = threadIdx.x;
    const int nh = blockIdx.y;
    const int n = nh >> 3, h = nh & 7;
    const int l0 = blockIdx.x * 64;

    const float* qp = g_q + (size_t)nh * L_ * D_;
    const float* vp = g_v + (size_t)nh * L_ * D_;
    const float* ap = g_attn + (size_t)nh * 4096;

    // attn: 1024 float4, 8/thread
#pragma unroll
    for (int p = 0; p < 8; p++) {
        int fi = tid + p * 128;
        int r = fi >> 4, c = (fi & 15) * 4;
        *(float4*)&attn_s[r][c] = *(const float4*)(ap + r * 64 + c);
    }
    // q: 64 rows -> 1024 float4, 8/thread
#pragma unroll
    for (int p = 0; p < 8; p++) {
        int fi = tid + p * 128;
        int r = fi >> 4, c = (fi & 15) * 4;
        *(float4*)&qs[r][c] = *(const float4*)(qp + (size_t)(l0 + r) * D_ + c);
    }
    if (tid < KS_) wc[tid] = wdc[h * KS_ + tid];
    __syncthreads();

    if (tid < 64) {
        float s = 0.f;
#pragma unroll
        for (int d = 0; d < 64; d++) {
            float x = qs[tid][d];
            s = fmaf(x, x, s);
        }
        invq[tid] = 1.0f / sqrtf(s);
    }
    __syncthreads();

    const int rg = tid >> 2;        // 0..31
    const int p4 = tid & 3;
    const int e0 = p4 * 16;
    const int r0 = rg * 2;          // rows r0, r0+1 within block

    // --- matvec q @ attn for both rows ---
    float acc0[16], acc1[16];
#pragma unroll
    for (int j = 0; j < 16; j++) { acc0[j] = 0.f; acc1[j] = 0.f; }

#pragma unroll 8
    for (int d = 0; d < 64; d++) {
        float q0 = qs[r0][d];
        float q1 = qs[r0 + 1][d];
#pragma unroll
        for (int jc = 0; jc < 4; jc++) {
            float4 a = *(const float4*)&attn_s[d][e0 + jc * 4];
            acc0[jc * 4 + 0] = fmaf(q0, a.x, acc0[jc * 4 + 0]);
            acc0[jc * 4 + 1] = fmaf(q0, a.y, acc0[jc * 4 + 1]);
            acc0[jc * 4 + 2] = fmaf(q0, a.z, acc0[jc * 4 + 2]);
            acc0[jc * 4 + 3] = fmaf(q0, a.w, acc0[jc * 4 + 3]);
            acc1[jc * 4 + 0] = fmaf(q1, a.x, acc1[jc * 4 + 0]);
            acc1[jc * 4 + 1] = fmaf(q1, a.y, acc1[jc * 4 + 1]);
            acc1[jc * 4 + 2] = fmaf(q1, a.z, acc1[jc * 4 + 2]);
            acc1[jc * 4 + 3] = fmaf(q1, a.w, acc1[jc * 4 + 3]);
        }
    }

    // --- v sliding window: conv taps + saved center rows ---
    float dc0[16], dc1[16], v0[16], v1[16];
#pragma unroll
    for (int j = 0; j < 16; j++) { dc0[j] = 0.f; dc1[j] = 0.f; }

#pragma unroll
    for (int w = 0; w < 10; w++) {
        int gl = l0 + r0 - 4 + w;
        float row[16];
        if (gl >= 0 && gl < L_) {
#pragma unroll
            for (int jc = 0; jc < 4; jc++) {
                float4 t = *(const float4*)(vp + (size_t)gl * D_ + e0 + jc * 4);
                row[jc * 4 + 0] = t.x; row[jc * 4 + 1] = t.y;
                row[jc * 4 + 2] = t.z; row[jc * 4 + 3] = t.w;
            }
        } else {
#pragma unroll
            for (int j = 0; j < 16; j++) row[j] = 0.f;
        }
        if (w < 9) {
            float wt = wc[w];
#pragma unroll
            for (int j = 0; j < 16; j++) dc0[j] = fmaf(wt, row[j], dc0[j]);
        }
        if (w >= 1) {
            float wt = wc[w - 1];
#pragma unroll
            for (int j = 0; j < 16; j++) dc1[j] = fmaf(wt, row[j], dc1[j]);
        }
        if (w == 4) {
#pragma unroll
            for (int j = 0; j < 16; j++) v0[j] = row[j];
        }
        if (w == 5) {
#pragma unroll
            for (int j = 0; j < 16; j++) v1[j] = row[j];
        }
    }

    // --- pre = 0.5 v + acc/||q|| ; row l2 norm; add conv; store ---
    float iq0 = invq[r0], iq1 = invq[r0 + 1];
    float pre0[16], pre1[16];
    float ssq0 = 0.f, ssq1 = 0.f;
#pragma unroll
    for (int j = 0; j < 16; j++) {
        float p0 = fmaf(0.5f, v0[j], acc0[j] * iq0);
        float p1 = fmaf(0.5f, v1[j], acc1[j] * iq1);
        pre0[j] = p0; pre1[j] = p1;
        ssq0 = fmaf(p0, p0, ssq0);
        ssq1 = fmaf(p1, p1, ssq1);
    }
    // reduce across the 4 threads owning each row (consecutive lanes)
    ssq0 += __shfl_xor_sync(0xffffffffu, ssq0, 1);
    ssq0 += __shfl_xor_sync(0xffffffffu, ssq0, 2);
    ssq1 += __shfl_xor_sync(0xffffffffu, ssq1, 1);
    ssq1 += __shfl_xor_sync(0xffffffffu, ssq1, 2);
    float inv0 = 1.0f / sqrtf(ssq0);
    float inv1 = 1.0f / sqrtf(ssq1);

    float* mp0 = g_mid + ((size_t)(n * L_ + l0 + r0)) * C_ + h * D_ + e0;
    float* mp1 = mp0 + C_;
#pragma unroll
    for (int jc = 0; jc < 4; jc++) {
        float4 o0, o1;
        o0.x = fmaf(pre0[jc * 4 + 0], inv0, dc0[jc * 4 + 0]);
        o0.y = fmaf(pre0[jc * 4 + 1], inv0, dc0[jc * 4 + 1]);
        o0.z = fmaf(pre0[jc * 4 + 2], inv0, dc0[jc * 4 + 2]);
        o0.w = fmaf(pre0[jc * 4 + 3], inv0, dc0[jc * 4 + 3]);
        o1.x = fmaf(pre1[jc * 4 + 0], inv1, dc1[jc * 4 + 0]);
        o1.y = fmaf(pre1[jc * 4 + 1], inv1, dc1[jc * 4 + 1]);
        o1.z = fmaf(pre1[jc * 4 + 2], inv1, dc1[jc * 4 + 2]);
        o1.w = fmaf(pre1[jc * 4 + 3], inv1, dc1[jc * 4 + 3]);
        *(float4*)(mp0 + jc * 4) = o0;
        *(float4*)(mp1 + jc * 4) = o1;
    }
}

// ---------------------------------------------------------------------------
extern "C" void kernel_launch(void* const* d_in, const int* in_sizes, int n_in,
                              void* d_out, int out_size)
{
    const float* x       = (const float*)d_in[0];   // [4,4096,512]
    const float* w_qkv   = (const float*)d_in[1];   // [512,1536]
    const float* b_qkv   = (const float*)d_in[2];   // [1536]
    const float* w_dconv = (const float*)d_in[3];   // [8,1,9,1]
    const float* w_proj  = (const float*)d_in[4];   // [512,512]
    const float* b_proj  = (const float*)d_in[5];   // [512]
    float* out = (float*)d_out;                      // [4,4096,512]

    const int M = NB * L_;       // 16384

    // 1. QKV projection (TF32 tensor cores), scatter to q/k/v [N,H,L,D]
    tf32_gemm_kernel<0><<<dim3((3 * C_) / 128, M / 128), 256>>>(
        x, w_qkv, b_qkv, nullptr, M, 3 * C_, C_);

    // 2. attn partials: k l2norm fused; split-L
    kv_attn_partial_kernel<<<dim3(SPLITS, NHT), 256>>>();

    // 3. deterministic reduce (+ INV_PI fold)
    attn_reduce_kernel<<<(NHT * D_ * D_) / 256, 256>>>();

    // 4. fused: q@attn, 0.5v, row l2norm, depthwise conv, layout->[N,L,C]
    out_kernel<<<dim3(L_ / 64, NHT), 128>>>(w_dconv);

    // 5. output projection (TF32 tensor cores) -> d_out
    tf32_gemm_kernel<1><<<dim3(C_ / 128, M / 128), 256>>>(
        nullptr, w_proj, b_proj, out, M, C_, C_);
}

// round 6
// speedup vs baseline: 2.3958x; 1.1280x over previous
#include <cuda_runtime.h>

// Problem constants
#define L_   4096
#define C_   512
#define H_   8
#define D_   64
#define NB   4
#define NHT  32            // NB * H_
#define KS_  9
#define ASPL 8             // attn L-splits
#define INV_PI 0.31830988618379067154f

// Scratch (static device globals — allocation-free per harness rules)
__device__ float g_q[(size_t)NB * H_ * L_ * D_];
__device__ float g_k[(size_t)NB * H_ * L_ * D_];
__device__ float g_v[(size_t)NB * H_ * L_ * D_];
__device__ float g_part[(size_t)ASPL * NHT * D_ * D_];
__device__ float g_attn[(size_t)NHT * D_ * D_];
__device__ float g_mid[(size_t)NB * L_ * C_];

// ---------------------------------------------------------------------------
// TF32 helpers (fragment conventions validated in Round 3/4 GEMM)
// ---------------------------------------------------------------------------
__device__ __forceinline__ float f2tf(float x) {
    unsigned y;
    asm("cvt.rna.tf32.f32 %0, %1;" : "=r"(y) : "f"(x));
    return __uint_as_float(y);
}
__device__ __forceinline__ unsigned f2tfb(float x) {
    unsigned y;
    asm("cvt.rna.tf32.f32 %0, %1;" : "=r"(y) : "f"(x));
    return y;
}

__device__ __forceinline__ void mma_tf32(float* c, const unsigned* a, const unsigned* b) {
    asm volatile(
        "mma.sync.aligned.m16n8k8.row.col.f32.tf32.tf32.f32 "
        "{%0,%1,%2,%3}, {%4,%5,%6,%7}, {%8,%9}, {%0,%1,%2,%3};\n"
        : "+f"(c[0]), "+f"(c[1]), "+f"(c[2]), "+f"(c[3])
        : "r"(a[0]), "r"(a[1]), "r"(a[2]), "r"(a[3]),
          "r"(b[0]), "r"(b[1]));
}

// ---------------------------------------------------------------------------
// TF32 tensor-core GEMM: C[M,N] = A[M,K] @ B[K,N] + bias[N]
// MODE 0: epilogue scatters into g_q/g_k/g_v as [N,H,L,D]   (QKV projection)
// MODE 1: A is g_mid, epilogue writes Cout row-major        (output projection)
// (unchanged — passing at rel_err 4.9e-4, 515 µs total)
// ---------------------------------------------------------------------------
template <int MODE>
__global__ __launch_bounds__(256) void tf32_gemm_kernel(
    const float* __restrict__ A, const float* __restrict__ B,
    const float* __restrict__ bias, float* __restrict__ Cout,
    int M, int N, int K)
{
    __shared__ alignas(16) float As[2][16][132];
    __shared__ alignas(16) float Bs[2][16][132];

    const float* Aptr = (MODE == 1) ? (const float*)g_mid : A;

    const int tid = threadIdx.x;
    const int lane = tid & 31;
    const int warp = tid >> 5;
    const int warp_m = warp >> 2;
    const int warp_n = warp & 3;
    const int g = lane >> 2;
    const int tig = lane & 3;

    const int bn = blockIdx.x;
    const int bm = blockIdx.y;

    const int arow = tid >> 2;
    const int acol = (tid & 3) * 4;
    const int brow = tid >> 5;
    const int bcol = (tid & 31) * 4;

    const float* Ablk = Aptr + (size_t)bm * 128 * K;
    const float* Bblk = B + (size_t)bn * 128;

    float acc[4][4][4];
#pragma unroll
    for (int mt = 0; mt < 4; mt++)
#pragma unroll
        for (int nt = 0; nt < 4; nt++)
#pragma unroll
            for (int i = 0; i < 4; i++) acc[mt][nt][i] = 0.f;

    {
#pragma unroll
        for (int p = 0; p < 2; p++) {
            int r = arow + 64 * p;
            float4 t = *(const float4*)(Ablk + (size_t)r * K + acol);
            As[0][acol + 0][r] = f2tf(t.x);
            As[0][acol + 1][r] = f2tf(t.y);
            As[0][acol + 2][r] = f2tf(t.z);
            As[0][acol + 3][r] = f2tf(t.w);
        }
#pragma unroll
        for (int p = 0; p < 2; p++) {
            int r = brow + 8 * p;
            float4 t = *(const float4*)(Bblk + (size_t)r * N + bcol);
            float4 c = make_float4(f2tf(t.x), f2tf(t.y), f2tf(t.z), f2tf(t.w));
            *(float4*)&Bs[0][r][bcol] = c;
        }
    }
    __syncthreads();

    int buf = 0;
    for (int kk = 0; kk < K; kk += 16) {
        const bool has_next = (kk + 16) < K;
        float4 pa0, pa1, pb0, pb1;
        if (has_next) {
            pa0 = *(const float4*)(Ablk + (size_t)arow * K + (kk + 16) + acol);
            pa1 = *(const float4*)(Ablk + (size_t)(arow + 64) * K + (kk + 16) + acol);
            pb0 = *(const float4*)(Bblk + (size_t)(kk + 16 + brow) * N + bcol);
            pb1 = *(const float4*)(Bblk + (size_t)(kk + 16 + brow + 8) * N + bcol);
        }

        const float (*Asb)[132] = As[buf];
        const float (*Bsb)[132] = Bs[buf];
#pragma unroll
        for (int ks = 0; ks < 2; ks++) {
            const int k0 = ks * 8;
            unsigned af[4][4], bf[4][2];
#pragma unroll
            for (int mt = 0; mt < 4; mt++) {
                int m0 = warp_m * 64 + mt * 16 + g;
                af[mt][0] = __float_as_uint(Asb[k0 + tig][m0]);
                af[mt][1] = __float_as_uint(Asb[k0 + tig][m0 + 8]);
                af[mt][2] = __float_as_uint(Asb[k0 + tig + 4][m0]);
                af[mt][3] = __float_as_uint(Asb[k0 + tig + 4][m0 + 8]);
            }
#pragma unroll
            for (int nt = 0; nt < 4; nt++) {
                int n0 = warp_n * 32 + nt * 8 + g;
                bf[nt][0] = __float_as_uint(Bsb[k0 + tig][n0]);
                bf[nt][1] = __float_as_uint(Bsb[k0 + tig + 4][n0]);
            }
#pragma unroll
            for (int mt = 0; mt < 4; mt++)
#pragma unroll
                for (int nt = 0; nt < 4; nt++)
                    mma_tf32(acc[mt][nt], af[mt], bf[nt]);
        }

        if (has_next) {
            int nb = buf ^ 1;
            As[nb][acol + 0][arow] = f2tf(pa0.x);
            As[nb][acol + 1][arow] = f2tf(pa0.y);
            As[nb][acol + 2][arow] = f2tf(pa0.z);
            As[nb][acol + 3][arow] = f2tf(pa0.w);
            As[nb][acol + 0][arow + 64] = f2tf(pa1.x);
            As[nb][acol + 1][arow + 64] = f2tf(pa1.y);
            As[nb][acol + 2][arow + 64] = f2tf(pa1.z);
            As[nb][acol + 3][arow + 64] = f2tf(pa1.w);
            float4 c0 = make_float4(f2tf(pb0.x), f2tf(pb0.y), f2tf(pb0.z), f2tf(pb0.w));
            float4 c1 = make_float4(f2tf(pb1.x), f2tf(pb1.y), f2tf(pb1.z), f2tf(pb1.w));
            *(float4*)&Bs[nb][brow][bcol] = c0;
            *(float4*)&Bs[nb][brow + 8][bcol] = c1;
            __syncthreads();
            buf = nb;
        }
    }

#pragma unroll
    for (int mt = 0; mt < 4; mt++) {
        int r0 = bm * 128 + warp_m * 64 + mt * 16 + g;
#pragma unroll
        for (int nt = 0; nt < 4; nt++) {
            int col = bn * 128 + warp_n * 32 + nt * 8 + 2 * tig;
            float b0 = bias[col];
            float b1 = bias[col + 1];
            float2 v01 = make_float2(acc[mt][nt][0] + b0, acc[mt][nt][1] + b1);
            float2 v23 = make_float2(acc[mt][nt][2] + b0, acc[mt][nt][3] + b1);
            if (MODE == 0) {
                int s = col >> 9;
                int h = (col >> 6) & 7;
                int d = col & 63;
                float* dst = (s == 0) ? g_q : ((s == 1) ? g_k : g_v);
                int n0r = r0 >> 12, l0r = r0 & (L_ - 1);
                size_t base = (((size_t)n0r * H_ + h) * L_) * D_ + d;
                *(float2*)(dst + base + (size_t)l0r * D_) = v01;
                *(float2*)(dst + base + (size_t)(l0r + 8) * D_) = v23;
            } else {
                *(float2*)(Cout + (size_t)r0 * N + col) = v01;
                *(float2*)(Cout + (size_t)(r0 + 8) * N + col) = v23;
            }
        }
    }
}

// ---------------------------------------------------------------------------
// attn partial via tensor cores: for (n,h), attn[d,e] = sum_l knorm[l,d]*v[l,e]
// grid (ASPL, NHT), 256 thr = 8 warps; warp tile 16(d) x 32(e); 512 rows per
// block staged in 8 tiles of 64. k inv-norm folded into A fragments.
// ---------------------------------------------------------------------------
__global__ __launch_bounds__(256) void attn_mma_kernel()
{
    __shared__ alignas(16) float ks[64][68];
    __shared__ alignas(16) float vs[64][68];
    __shared__ float invn[64];

    const int tid = threadIdx.x;
    const int split = blockIdx.x;
    const int nh = blockIdx.y;
    const int lane = tid & 31;
    const int warp = tid >> 5;
    const int warp_m = warp >> 1;      // 0..3 : d-tile
    const int warp_n = warp & 1;       // 0..1 : e half
    const int g = lane >> 2;
    const int tig = lane & 3;

    const float* kp = g_k + (size_t)nh * L_ * D_;
    const float* vp = g_v + (size_t)nh * L_ * D_;

    float acc[4][4];
#pragma unroll
    for (int nt = 0; nt < 4; nt++)
#pragma unroll
        for (int i = 0; i < 4; i++) acc[nt][i] = 0.f;

    const int rr = tid >> 2;           // 0..63 (norm phase row)
    const int cc = tid & 3;

    for (int t = 0; t < 8; t++) {
        int l0 = split * (L_ / ASPL) + t * 64;
        // stage k,v (tf32-rounded): 1024 float4 each, 4 per thread
#pragma unroll
        for (int p = 0; p < 4; p++) {
            int fi = tid + p * 256;
            int r = fi >> 4, c = (fi & 15) * 4;
            float4 kt = *(const float4*)(kp + (size_t)(l0 + r) * D_ + c);
            float4 vt = *(const float4*)(vp + (size_t)(l0 + r) * D_ + c);
            ks[r][c + 0] = f2tf(kt.x); ks[r][c + 1] = f2tf(kt.y);
            ks[r][c + 2] = f2tf(kt.z); ks[r][c + 3] = f2tf(kt.w);
            vs[r][c + 0] = f2tf(vt.x); vs[r][c + 1] = f2tf(vt.y);
            vs[r][c + 2] = f2tf(vt.z); vs[r][c + 3] = f2tf(vt.w);
        }
        __syncthreads();

        // row inv-norms of k (4 lanes per row; norms from tf32 k — consistent
        // with reference to ~1e-4 since it's a 64-term positive sum)
        {
            float s = 0.f;
#pragma unroll
            for (int j = 0; j < 16; j++) {
                float x = ks[rr][cc * 16 + j];
                s = fmaf(x, x, s);
            }
            s += __shfl_xor_sync(0xffffffffu, s, 1);
            s += __shfl_xor_sync(0xffffffffu, s, 2);
            if (cc == 0) invn[rr] = 1.0f / sqrtf(s);
        }
        __syncthreads();

        // mma over this 64-row K tile
        const int d0 = warp_m * 16;
#pragma unroll
        for (int kstep = 0; kstep < 8; kstep++) {
            int k0 = kstep * 8;
            float s0 = invn[k0 + tig];
            float s1 = invn[k0 + tig + 4];
            unsigned a[4];
            a[0] = f2tfb(ks[k0 + tig][d0 + g] * s0);
            a[1] = f2tfb(ks[k0 + tig][d0 + g + 8] * s0);
            a[2] = f2tfb(ks[k0 + tig + 4][d0 + g] * s1);
            a[3] = f2tfb(ks[k0 + tig + 4][d0 + g + 8] * s1);
#pragma unroll
            for (int nt = 0; nt < 4; nt++) {
                int n0 = warp_n * 32 + nt * 8;
                unsigned b[2];
                b[0] = __float_as_uint(vs[k0 + tig][n0 + g]);
                b[1] = __float_as_uint(vs[k0 + tig + 4][n0 + g]);
                mma_tf32(acc[nt], a, b);
            }
        }
        __syncthreads();
    }

    // write partial [d, e]
    float* out = g_part + ((size_t)split * NHT + nh) * (D_ * D_);
    const int dA = warp_m * 16 + g;
    const int dB = dA + 8;
#pragma unroll
    for (int nt = 0; nt < 4; nt++) {
        int e = warp_n * 32 + nt * 8 + 2 * tig;
        *(float2*)&out[dA * 64 + e] = make_float2(acc[nt][0], acc[nt][1]);
        *(float2*)&out[dB * 64 + e] = make_float2(acc[nt][2], acc[nt][3]);
    }
}

// Deterministic reduction of split partials; folds INV_PI into attn.
__global__ __launch_bounds__(256) void attn_reduce_kernel()
{
    int idx = blockIdx.x * 256 + threadIdx.x;
    int nh = idx >> 12;
    int rem = idx & 4095;
    float s = 0.f;
#pragma unroll
    for (int sp = 0; sp < ASPL; sp++)
        s += g_part[((size_t)sp * NHT + nh) * 4096 + rem];
    g_attn[idx] = INV_PI * s;
}

// ---------------------------------------------------------------------------
// out kernel v3 (tensor cores): per (nh, 64-row L tile):
//   acc = q @ attn (tf32 mma, warp tile 16x32; attn has INV_PI folded)
//   pre = 0.5*v + acc/||q||  (fp32, fragment layout) -> written into sm_a
//   ssq reduced via shfl + smem; then coalesced: out = pre/||pre|| + conv9(v)
// Dynamic smem ~55 KB (opt-in attribute, set once on host).
// ---------------------------------------------------------------------------
#define OQ(r, c)  sm_q[(r) * 68 + (c)]
#define OA(r, c)  sm_a[(r) * 68 + (c)]
#define OV(r, c)  sm_v[(r) * 68 + (c)]
#define OUT_SMEM_FLOATS (64 * 68 + 64 * 68 + 72 * 68 + 64 + 128 + 16)

__global__ __launch_bounds__(256) void out_kernel(const float* __restrict__ wdc)
{
    extern __shared__ float sm[];
    float* sm_q = sm;                       // [64][68] q (tf32)
    float* sm_a = sm_q + 64 * 68;           // [64][68] attn (tf32) -> pre (fp32)
    float* sm_v = sm_a + 64 * 68;           // [72][68] v raw, rows l0-4..l0+67
    float* invq = sm_v + 72 * 68;           // [64]
    float* ssq_s = invq + 64;               // [2][64]
    float* wc = ssq_s + 128;                // [16]

    const int tid = threadIdx.x;
    const int nh = blockIdx.y;
    const int n = nh >> 3, h = nh & 7;
    const int l0 = blockIdx.x * 64;

    const float* qp = g_q + (size_t)nh * L_ * D_;
    const float* vp = g_v + (size_t)nh * L_ * D_;
    const float* ap = g_attn + (size_t)nh * 4096;

    // stage attn + q (tf32)
#pragma unroll
    for (int p = 0; p < 4; p++) {
        int fi = tid + p * 256;
        int r = fi >> 4, c = (fi & 15) * 4;
        float4 a = *(const float4*)(ap + r * 64 + c);
        OA(r, c + 0) = f2tf(a.x); OA(r, c + 1) = f2tf(a.y);
        OA(r, c + 2) = f2tf(a.z); OA(r, c + 3) = f2tf(a.w);
        float4 q = *(const float4*)(qp + (size_t)(l0 + r) * D_ + c);
        OQ(r, c + 0) = f2tf(q.x); OQ(r, c + 1) = f2tf(q.y);
        OQ(r, c + 2) = f2tf(q.z); OQ(r, c + 3) = f2tf(q.w);
    }
    // stage v with halo (raw fp32), 72 rows
    for (int fi = tid; fi < 72 * 16; fi += 256) {
        int r = fi >> 4, c = (fi & 15) * 4;
        int gl = l0 - 4 + r;
        float4 val = make_float4(0.f, 0.f, 0.f, 0.f);
        if (gl >= 0 && gl < L_)
            val = *(const float4*)(vp + (size_t)gl * D_ + c);
        *(float4*)&OV(r, c) = val;
    }
    if (tid < KS_) wc[tid] = wdc[h * KS_ + tid];
    __syncthreads();

    // q row inv-norms (4 lanes per row)
    {
        int rr = tid >> 2, cc = tid & 3;
        float s = 0.f;
#pragma unroll
        for (int j = 0; j < 16; j++) {
            float x = OQ(rr, cc * 16 + j);
            s = fmaf(x, x, s);
        }
        s += __shfl_xor_sync(0xffffffffu, s, 1);
        s += __shfl_xor_sync(0xffffffffu, s, 2);
        if (cc == 0) invq[rr] = 1.0f / sqrtf(s);
    }
    __syncthreads();

    // mma: out64x64 = q(64x64) @ attn(64x64); warp tile 16x32
    const int lane = tid & 31;
    const int warp = tid >> 5;
    const int warp_m = warp >> 1;      // 0..3
    const int warp_n = warp & 1;       // 0..1
    const int g = lane >> 2;
    const int tig = lane & 3;

    float acc[4][4];
#pragma unroll
    for (int nt = 0; nt < 4; nt++)
#pragma unroll
        for (int i = 0; i < 4; i++) acc[nt][i] = 0.f;

    const int m0 = warp_m * 16;
#pragma unroll
    for (int kstep = 0; kstep < 8; kstep++) {
        int k0 = kstep * 8;
        unsigned a[4];
        a[0] = __float_as_uint(OQ(m0 + g, k0 + tig));
        a[1] = __float_as_uint(OQ(m0 + g + 8, k0 + tig));
        a[2] = __float_as_uint(OQ(m0 + g, k0 + tig + 4));
        a[3] = __float_as_uint(OQ(m0 + g + 8, k0 + tig + 4));
#pragma unroll
        for (int nt = 0; nt < 4; nt++) {
            int n0 = warp_n * 32 + nt * 8;
            unsigned b[2];
            b[0] = __float_as_uint(OA(k0 + tig, n0 + g));
            b[1] = __float_as_uint(OA(k0 + tig + 4, n0 + g));
            mma_tf32(acc[nt], a, b);
        }
    }
    __syncthreads();   // all warps done reading attn buf before reuse as pre

    // epilogue: pre = 0.5 v + acc * invq ; partial ssq; write pre into sm_a
    {
        const int rA = warp_m * 16 + g;
        const int rB = rA + 8;
        const float iqA = invq[rA];
        const float iqB = invq[rB];
        float ssqA = 0.f, ssqB = 0.f;
#pragma unroll
        for (int nt = 0; nt < 4; nt++) {
            int c = warp_n * 32 + nt * 8 + 2 * tig;
            float2 vA = *(const float2*)&OV(4 + rA, c);
            float2 vB = *(const float2*)&OV(4 + rB, c);
            float pA0 = fmaf(0.5f, vA.x, acc[nt][0] * iqA);
            float pA1 = fmaf(0.5f, vA.y, acc[nt][1] * iqA);
            float pB0 = fmaf(0.5f, vB.x, acc[nt][2] * iqB);
            float pB1 = fmaf(0.5f, vB.y, acc[nt][3] * iqB);
            ssqA = fmaf(pA0, pA0, ssqA); ssqA = fmaf(pA1, pA1, ssqA);
            ssqB = fmaf(pB0, pB0, ssqB); ssqB = fmaf(pB1, pB1, ssqB);
            *(float2*)&OA(rA, c) = make_float2(pA0, pA1);
            *(float2*)&OA(rB, c) = make_float2(pB0, pB1);
        }
        ssqA += __shfl_xor_sync(0xffffffffu, ssqA, 1);
        ssqA += __shfl_xor_sync(0xffffffffu, ssqA, 2);
        ssqB += __shfl_xor_sync(0xffffffffu, ssqB, 1);
        ssqB += __shfl_xor_sync(0xffffffffu, ssqB, 2);
        if (tig == 0) {
            ssq_s[warp_n * 64 + rA] = ssqA;
            ssq_s[warp_n * 64 + rB] = ssqB;
        }
    }
    __syncthreads();

    // final coalesced phase: norm + depthwise conv + store [N,L,C]
    {
        const int r = tid >> 2;
        const int e0 = (tid & 3) * 16;
        float inv2 = 1.0f / sqrtf(ssq_s[r] + ssq_s[64 + r]);

        float dc[16];
#pragma unroll
        for (int j = 0; j < 16; j++) dc[j] = 0.f;
#pragma unroll
        for (int t = 0; t < KS_; t++) {
            float w = wc[t];
#pragma unroll
            for (int jc = 0; jc < 4; jc++) {
                float4 vv = *(const float4*)&OV(r + t, e0 + jc * 4);
                dc[jc * 4 + 0] = fmaf(w, vv.x, dc[jc * 4 + 0]);
                dc[jc * 4 + 1] = fmaf(w, vv.y, dc[jc * 4 + 1]);
                dc[jc * 4 + 2] = fmaf(w, vv.z, dc[jc * 4 + 2]);
                dc[jc * 4 + 3] = fmaf(w, vv.w, dc[jc * 4 + 3]);
            }
        }

        float* mp = g_mid + ((size_t)(n * L_ + l0 + r)) * C_ + h * D_ + e0;
#pragma unroll
        for (int jc = 0; jc < 4; jc++) {
            float4 p = *(const float4*)&OA(r, e0 + jc * 4);
            float4 o;
            o.x = fmaf(p.x, inv2, dc[jc * 4 + 0]);
            o.y = fmaf(p.y, inv2, dc[jc * 4 + 1]);
            o.z = fmaf(p.z, inv2, dc[jc * 4 + 2]);
            o.w = fmaf(p.w, inv2, dc[jc * 4 + 3]);
            *(float4*)(mp + jc * 4) = o;
        }
    }
}

// ---------------------------------------------------------------------------
extern "C" void kernel_launch(void* const* d_in, const int* in_sizes, int n_in,
                              void* d_out, int out_size)
{
    const float* x       = (const float*)d_in[0];   // [4,4096,512]
    const float* w_qkv   = (const float*)d_in[1];   // [512,1536]
    const float* b_qkv   = (const float*)d_in[2];   // [1536]
    const float* w_dconv = (const float*)d_in[3];   // [8,1,9,1]
    const float* w_proj  = (const float*)d_in[4];   // [512,512]
    const float* b_proj  = (const float*)d_in[5];   // [512]
    float* out = (float*)d_out;                      // [4,4096,512]

    const int M = NB * L_;       // 16384
    const int out_smem = OUT_SMEM_FLOATS * (int)sizeof(float);  // ~55 KB

    // One-time attribute opt-in (host-side, idempotent; kept out of the
    // steady-state capture path so captured graphs contain launches only).
    static bool attr_done = false;
    if (!attr_done) {
        cudaFuncSetAttribute(out_kernel,
                             cudaFuncAttributeMaxDynamicSharedMemorySize, out_smem);
        attr_done = true;
    }

    // 1. QKV projection (TF32 tensor cores), scatter to q/k/v [N,H,L,D]
    tf32_gemm_kernel<0><<<dim3((3 * C_) / 128, M / 128), 256>>>(
        x, w_qkv, b_qkv, nullptr, M, 3 * C_, C_);

    // 2. attn partials on tensor cores (k l2norm folded into A frags)
    attn_mma_kernel<<<dim3(ASPL, NHT), 256>>>();

    // 3. deterministic reduce (+ INV_PI fold)
    attn_reduce_kernel<<<(NHT * D_ * D_) / 256, 256>>>();

    // 4. fused mma out stage: q@attn, 0.5v, row l2norm, conv9, -> [N,L,C]
    out_kernel<<<dim3(L_ / 64, NHT), 256, out_smem>>>(w_dconv);

    // 5. output projection (TF32 tensor cores) -> d_out
    tf32_gemm_kernel<1><<<dim3(C_ / 128, M / 128), 256>>>(
        nullptr, w_proj, b_proj, out, M, C_, C_);
}